// round 1
// baseline (speedup 1.0000x reference)
#include <cuda_runtime.h>
#include <cuda_bf16.h>
#include <math.h>

// Problem dims
#define TT 256
#define BB 16
#define SS 64
#define DD 256
#define GRP 8          // CTAs per batch group (e-split)
#define NC 32          // e-columns per CTA
#define NCTA (BB*GRP)  // 128
#define NTHR 256

#define BSD (BB*SS*DD)     // 262144
#define TBD (TT*BB*DD)     // 1048576

// Scratch (device globals; allocation-free rule)
__device__ float g_wxb[TBD];          // Wx@x + bias, [t][b][e]
__device__ float g_sz[TBD];           // silu(z),    [t][b][e]
__device__ unsigned g_bar[BB];        // monotonic per-group barriers

// Dynamic smem layout (floats)
#define A_OFF   0          // a_s[64][256]      16384
#define W_OFF   16384      // w_s[k=256][e=32]   8192
#define RED_OFF 24576      // red[8][32]          256
#define CS_OFF  24832      // C[64]                64
#define SMEM_FLOATS 24896
// prologue reuse: wch[256][68] at 0 (17408), xch[32][64] at 17408 (2048)

__device__ __forceinline__ float fast_tanh(float x) {
    float ax = fabsf(x);
    float e  = __expf(-2.0f * ax);
    float r  = __fdividef(1.0f - e, 1.0f + e);
    return copysignf(r, x);
}

__device__ __forceinline__ void group_barrier(int b, int tid) {
    __syncthreads();
    if (tid == 0) {
        __threadfence();
        unsigned old = atomicAdd(&g_bar[b], 1u);
        unsigned target = (old / GRP + 1u) * GRP;
        while (*((volatile unsigned*)&g_bar[b]) < target) { }
        __threadfence();
    }
    __syncthreads();
}

__global__ __launch_bounds__(NTHR, 1)
void slot_elman_kernel(const float* __restrict__ x,
                       const float* __restrict__ z,
                       const float* __restrict__ h0,
                       const float* __restrict__ Wx,
                       const float* __restrict__ Wh,
                       const float* __restrict__ bias,
                       const float* __restrict__ C,
                       float* __restrict__ d_out) {
    extern __shared__ float sm[];
    const int tid = threadIdx.x;
    const int b   = blockIdx.x / GRP;   // batch group
    const int m   = blockIdx.x % GRP;   // member (e-slice)
    const int ebase = m * NC;

    float* out_p = d_out;               // [T][B][D]
    float* h_p   = d_out + TBD;         // [T+1][B][S][D]

    // ---------------- Prologue ----------------
    // 1) wxb[t][b][:] for t in [m*32, m*32+32):  x_row @ Wx^T + bias
    {
        float* wch = sm;            // [256][68] padded
        float* xch = sm + 17408;    // [32][64]
        float pacc[32];
        #pragma unroll
        for (int i = 0; i < 32; i++) pacc[i] = 0.0f;

        for (int kt = 0; kt < 4; kt++) {
            const int k0 = kt * 64;
            __syncthreads();
            // load W chunk: wch[e][k] (padded rows of 68)
            for (int idx = tid; idx < 256 * 16; idx += NTHR) {
                int e = idx >> 4, q = idx & 15;
                float4 v = *(const float4*)(Wx + e * DD + k0 + q * 4);
                *(float4*)(wch + e * 68 + q * 4) = v;
            }
            // load x chunk: xch[i][k]
            for (int idx = tid; idx < 32 * 16; idx += NTHR) {
                int i = idx >> 4, q = idx & 15;
                int t = m * 32 + i;
                float4 v = *(const float4*)(x + (t * BB + b) * DD + k0 + q * 4);
                *(float4*)(xch + i * 64 + q * 4) = v;
            }
            __syncthreads();
            // thread owns output column e = tid
            for (int q = 0; q < 16; q++) {
                float4 wv = *(const float4*)(wch + tid * 68 + q * 4);
                #pragma unroll
                for (int i = 0; i < 32; i++) {
                    float4 xv = *(const float4*)(xch + i * 64 + q * 4);
                    pacc[i] += wv.x * xv.x + wv.y * xv.y + wv.z * xv.z + wv.w * xv.w;
                }
            }
        }
        float bb = bias[tid];
        #pragma unroll
        for (int i = 0; i < 32; i++) {
            int t = m * 32 + i;
            g_wxb[(t * BB + b) * DD + tid] = pacc[i] + bb;
        }
    }
    // 2) silu(z) for the same t-rows
    for (int idx = tid; idx < 32 * 64; idx += NTHR) {  // float4 count
        int i = idx >> 6, q = idx & 63;
        int t = m * 32 + i;
        float4 zv = *(const float4*)(z + (t * BB + b) * DD + q * 4);
        float4 sv;
        sv.x = __fdividef(zv.x, 1.0f + __expf(-zv.x));
        sv.y = __fdividef(zv.y, 1.0f + __expf(-zv.y));
        sv.z = __fdividef(zv.z, 1.0f + __expf(-zv.z));
        sv.w = __fdividef(zv.w, 1.0f + __expf(-zv.w));
        *(float4*)(g_sz + (t * BB + b) * DD + q * 4) = sv;
    }
    // 3) h[0] = h0 (member m copies 8 s-rows of its batch)
    {
        const float* src = h0 + b * (SS * DD) + (m * 8) * DD;
        float*       dst = h_p + b * (SS * DD) + (m * 8) * DD;
        for (int idx = tid; idx < 8 * 64; idx += NTHR) {
            *(float4*)(dst + idx * 4) = *(const float4*)(src + idx * 4);
        }
    }
    __syncthreads();

    // ---------------- Load resident Wh slice + C ----------------
    float* a_s = sm + A_OFF;
    float* w_s = sm + W_OFF;   // [k][e] : w_s[k*32+e] = Wh[(ebase+e)*256 + k]
    float* red = sm + RED_OFF;
    float* C_s = sm + CS_OFF;
    for (int idx = tid; idx < DD * NC; idx += NTHR) {
        int k = idx >> 5, e = idx & 31;
        w_s[idx] = Wh[(ebase + e) * DD + k];
    }
    if (tid < SS) C_s[tid] = C[tid];

    group_barrier(b, tid);  // prologue complete across the group

    // thread mapping: te = e-group (0..7, 4 cols each), ts = s-group (0..31, 2 rows each)
    const int te = tid & 7;
    const int ts = tid >> 3;
    const int s0 = ts * 2;
    const int te4 = te * 4;

    // ---------------- Main recurrence ----------------
    for (int t = 0; t < TT; t++) {
        // stage h_prev[b] into smem
        const float* hsrc = h_p + t * BSD + b * (SS * DD);
        for (int idx = tid; idx < SS * 64; idx += NTHR) {  // 4096 float4
            int s = idx >> 6, q = idx & 63;
            *(float4*)(a_s + s * DD + q * 4) = *(const float4*)(hsrc + s * DD + q * 4);
        }
        __syncthreads();

        // GEMM: acc[2 s][4 e] over K=256
        float acc00=0,acc01=0,acc02=0,acc03=0;
        float acc10=0,acc11=0,acc12=0,acc13=0;
        const float* ar0 = a_s + s0 * DD;
        const float* ar1 = a_s + (s0 + 1) * DD;
        #pragma unroll 2
        for (int k = 0; k < DD; k += 4) {
            float4 a0 = *(const float4*)(ar0 + k);
            float4 a1 = *(const float4*)(ar1 + k);
            float4 w0 = *(const float4*)(w_s + (k + 0) * NC + te4);
            float4 w1 = *(const float4*)(w_s + (k + 1) * NC + te4);
            float4 w2 = *(const float4*)(w_s + (k + 2) * NC + te4);
            float4 w3 = *(const float4*)(w_s + (k + 3) * NC + te4);
            acc00 += a0.x*w0.x; acc01 += a0.x*w0.y; acc02 += a0.x*w0.z; acc03 += a0.x*w0.w;
            acc10 += a1.x*w0.x; acc11 += a1.x*w0.y; acc12 += a1.x*w0.z; acc13 += a1.x*w0.w;
            acc00 += a0.y*w1.x; acc01 += a0.y*w1.y; acc02 += a0.y*w1.z; acc03 += a0.y*w1.w;
            acc10 += a1.y*w1.x; acc11 += a1.y*w1.y; acc12 += a1.y*w1.z; acc13 += a1.y*w1.w;
            acc00 += a0.z*w2.x; acc01 += a0.z*w2.y; acc02 += a0.z*w2.z; acc03 += a0.z*w2.w;
            acc10 += a1.z*w2.x; acc11 += a1.z*w2.y; acc12 += a1.z*w2.z; acc13 += a1.z*w2.w;
            acc00 += a0.w*w3.x; acc01 += a0.w*w3.y; acc02 += a0.w*w3.z; acc03 += a0.w*w3.w;
            acc10 += a1.w*w3.x; acc11 += a1.w*w3.y; acc12 += a1.w*w3.z; acc13 += a1.w*w3.w;
        }

        // Epilogue: tanh(acc + wxb), store h, partial C-weighted sums
        float4 wb = *(const float4*)(g_wxb + (t * BB + b) * DD + ebase + te4);
        float h00 = fast_tanh(acc00 + wb.x);
        float h01 = fast_tanh(acc01 + wb.y);
        float h02 = fast_tanh(acc02 + wb.z);
        float h03 = fast_tanh(acc03 + wb.w);
        float h10 = fast_tanh(acc10 + wb.x);
        float h11 = fast_tanh(acc11 + wb.y);
        float h12 = fast_tanh(acc12 + wb.z);
        float h13 = fast_tanh(acc13 + wb.w);

        float* hdst = h_p + (t + 1) * BSD + b * (SS * DD);
        *(float4*)(hdst + s0 * DD + ebase + te4)       = make_float4(h00, h01, h02, h03);
        *(float4*)(hdst + (s0 + 1) * DD + ebase + te4) = make_float4(h10, h11, h12, h13);

        float c0 = C_s[s0], c1 = C_s[s0 + 1];
        float p0 = h00 * c0 + h10 * c1;
        float p1 = h01 * c0 + h11 * c1;
        float p2 = h02 * c0 + h12 * c1;
        float p3 = h03 * c0 + h13 * c1;
        // reduce over the 4 ts-groups inside each warp (lanes differing in bits 3,4)
        p0 += __shfl_xor_sync(0xffffffffu, p0, 8);
        p1 += __shfl_xor_sync(0xffffffffu, p1, 8);
        p2 += __shfl_xor_sync(0xffffffffu, p2, 8);
        p3 += __shfl_xor_sync(0xffffffffu, p3, 8);
        p0 += __shfl_xor_sync(0xffffffffu, p0, 16);
        p1 += __shfl_xor_sync(0xffffffffu, p1, 16);
        p2 += __shfl_xor_sync(0xffffffffu, p2, 16);
        p3 += __shfl_xor_sync(0xffffffffu, p3, 16);
        if ((tid & 31) < 8) {
            int w = tid >> 5;
            *(float4*)(red + w * NC + te4) = make_float4(p0, p1, p2, p3);
        }
        __syncthreads();
        if (tid < NC) {
            float s = 0.0f;
            #pragma unroll
            for (int w = 0; w < 8; w++) s += red[w * NC + tid];
            float szv = g_sz[(t * BB + b) * DD + ebase + tid];
            out_p[(t * BB + b) * DD + ebase + tid] = s * szv;
        }

        group_barrier(b, tid);  // h[t+1] globally visible to the whole group
    }
}

extern "C" void kernel_launch(void* const* d_in, const int* in_sizes, int n_in,
                              void* d_out, int out_size) {
    const float* x    = (const float*)d_in[0];
    const float* z    = (const float*)d_in[1];
    const float* h0   = (const float*)d_in[2];
    const float* Wx   = (const float*)d_in[3];
    const float* Wh   = (const float*)d_in[4];
    const float* bias = (const float*)d_in[5];
    const float* C    = (const float*)d_in[6];
    float* out = (float*)d_out;

    size_t smem = SMEM_FLOATS * sizeof(float);
    cudaFuncSetAttribute(slot_elman_kernel,
                         cudaFuncAttributeMaxDynamicSharedMemorySize, (int)smem);
    slot_elman_kernel<<<NCTA, NTHR, smem>>>(x, z, h0, Wx, Wh, bias, C, out);
}